// round 10
// baseline (speedup 1.0000x reference)
#include <cuda_runtime.h>
#include <cstdint>

// Depthwise 3D conv 3x3x3, SAME, stride 1.
// x: (4,16,112,112,64) f32 NDHWC ; w: (3,3,3,1,64) f32
//
// R9: R5 tile (2H x 7W, float2 lanes, 24 warps/SM) + R6 instruction diet
// (warp-uniform H-edge skips, immediate-offset addressing). One warp per
// pixel across channels (256B coalesced LDG.64). Packed fma.rn.f32x2.

typedef unsigned long long u64;

#define W_DIM   112
#define H_DIM   112
#define D_DIM   16
#define N_DIM   4
#define C2      32                  // float2 channel groups = warp lanes
#define WS      7
#define HS      2
#define WSEG    (W_DIM / WS)        // 16
#define HT2     (H_DIM / HS)        // 56
#define WPB     4                   // warps per block
#define TPB     (WPB * 32)          // 128

#define ROW_F2    (W_DIM * C2)                 // u64 per H-row (3584)
#define SLICE_F2  (H_DIM * W_DIM * C2)         // u64 per D-slice
#define IMG_F2    ((size_t)D_DIM * SLICE_F2)   // u64 per batch n

__device__ __forceinline__ void fma2(u64& d, u64 a, u64 b) {
    asm("fma.rn.f32x2 %0, %1, %2, %0;" : "+l"(d) : "l"(a), "l"(b));
}

__global__ void __launch_bounds__(TPB, 6)
dwconv3d_kernel(const u64* __restrict__ xin,
                const u64* __restrict__ win,
                u64* __restrict__ out)
{
    const int lane = threadIdx.x & 31;
    const int gw   = blockIdx.x * WPB + (threadIdx.x >> 5);

    const int wseg = gw & (WSEG - 1);          // 16
    int t          = gw >> 4;
    const int hp   = t % HT2;                  // 56
    t             /= HT2;
    const int d    = t & (D_DIM - 1);          // 16
    const int n    = t >> 4;                   // 4

    const int h0 = hp * HS;
    const int w0 = wseg * WS;
    const bool lv   = (wseg != 0);
    const bool rv   = (wseg != WSEG - 1);
    const bool htop = (hp != 0);
    const bool hbot = (hp != HT2 - 1);

    const u64* wb = win + lane;
    // base at (n, d=0, h0-1, w0-1, lane); row/col offsets are compile-time
    // immediates off per-kd slice pointers.
    const u64* xb = xin + (size_t)n * IMG_F2
                  + ((ptrdiff_t)(h0 - 1) * W_DIM + (w0 - 1)) * C2 + lane;

    u64 acc[HS][WS];
    #pragma unroll
    for (int i = 0; i < HS; i++)
        #pragma unroll
        for (int j = 0; j < WS; j++)
            acc[i][j] = 0ull;

    #pragma unroll
    for (int kd = 0; kd < 3; kd++) {
        const int id = d + kd - 1;
        if (id < 0 || id >= D_DIM) continue;       // warp-uniform

        u64 wgt[3][3];
        #pragma unroll
        for (int kh = 0; kh < 3; kh++)
            #pragma unroll
            for (int kw = 0; kw < 3; kw++)
                wgt[kh][kw] = wb[((kd * 3 + kh) * 3 + kw) * C2];

        const u64* xs = xb + (size_t)id * SLICE_F2;

        #pragma unroll
        for (int r = 0; r < HS + 2; r++) {
            // H-edge rows skipped warp-uniformly (their taps contribute zero)
            if (r == 0      && !htop) continue;
            if (r == HS + 1 && !hbot) continue;

            const u64* p = xs + r * ROW_F2;        // immediate-folded offsets

            u64 row[WS + 2];
            row[0] = lv ? p[0] : 0ull;
            #pragma unroll
            for (int j = 1; j <= WS; j++)
                row[j] = p[j * C2];
            row[WS + 1] = rv ? p[(WS + 1) * C2] : 0ull;

            #pragma unroll
            for (int oh = 0; oh < HS; oh++) {
                // input row ih = h0 + r - 1 feeds output oh with tap k = r - oh
                const int k = r - oh;
                if (k >= 0 && k < 3) {
                    #pragma unroll
                    for (int ow = 0; ow < WS; ow++)
                        #pragma unroll
                        for (int kw = 0; kw < 3; kw++)
                            fma2(acc[oh][ow], row[ow + kw], wgt[k][kw]);
                }
            }
        }
    }

    u64* o = out + (size_t)n * IMG_F2 + (size_t)d * SLICE_F2
           + ((size_t)h0 * W_DIM + w0) * C2 + lane;
    #pragma unroll
    for (int i = 0; i < HS; i++)
        #pragma unroll
        for (int j = 0; j < WS; j++)
            o[(i * W_DIM + j) * C2] = acc[i][j];
}

extern "C" void kernel_launch(void* const* d_in, const int* in_sizes, int n_in,
                              void* d_out, int out_size) {
    const u64* x = (const u64*)d_in[0];
    const u64* w = (const u64*)d_in[1];
    u64* o = (u64*)d_out;

    // total warps = N * D * HT2 * WSEG = 4*16*56*16 = 57344
    const int total_warps = N_DIM * D_DIM * HT2 * WSEG;
    dwconv3d_kernel<<<total_warps / WPB, TPB>>>(x, w, o);
}

// round 11
// speedup vs baseline: 1.0844x; 1.0844x over previous
#include <cuda_runtime.h>
#include <cstdint>

// Depthwise 3D conv 3x3x3, SAME, stride 1.
// x: (4,16,112,112,64) f32 NDHWC ; w: (3,3,3,1,64) f32
//
// R10: R5's branch-free predicated body (ptxas batches ~36 loads per kd
// plane -> high MLP, issue ~48%) + immediate-offset addressing (R6's alu
// diet) instead of per-row IMAD chains. 2(H) x 7(W) warp tile, float2
// channel lanes (one warp per pixel, 256B coalesced), 24 warps/SM.
// Halo handled ONLY via ternary-predicated loads - no intra-kernel branches
// besides the 3 warp-uniform kd-plane guards (same as R5).

typedef unsigned long long u64;

#define W_DIM   112
#define H_DIM   112
#define D_DIM   16
#define N_DIM   4
#define C2      32                  // float2 channel groups = warp lanes
#define WS      7
#define HS      2
#define WSEG    (W_DIM / WS)        // 16
#define HT2     (H_DIM / HS)        // 56
#define WPB     4                   // warps per block
#define TPB     (WPB * 32)          // 128

#define ROW_F2    (W_DIM * C2)                 // u64 per H-row (3584)
#define SLICE_F2  (H_DIM * W_DIM * C2)         // u64 per D-slice
#define IMG_F2    ((size_t)D_DIM * SLICE_F2)   // u64 per batch n

__device__ __forceinline__ void fma2(u64& d, u64 a, u64 b) {
    asm("fma.rn.f32x2 %0, %1, %2, %0;" : "+l"(d) : "l"(a), "l"(b));
}

__global__ void __launch_bounds__(TPB, 6)
dwconv3d_kernel(const u64* __restrict__ xin,
                const u64* __restrict__ win,
                u64* __restrict__ out)
{
    const int lane = threadIdx.x & 31;
    const int gw   = blockIdx.x * WPB + (threadIdx.x >> 5);

    const int wseg = gw & (WSEG - 1);          // 16
    int t          = gw >> 4;
    const int hp   = t % HT2;                  // 56
    t             /= HT2;
    const int d    = t & (D_DIM - 1);          // 16
    const int n    = t >> 4;                   // 4

    const int h0 = hp * HS;
    const int w0 = wseg * WS;
    const bool lv   = (wseg != 0);
    const bool rv   = (wseg != WSEG - 1);
    const bool htop = (hp != 0);
    const bool hbot = (hp != HT2 - 1);

    const u64* wb = win + lane;
    // base at (n, d=0, h0-1, w0-1, lane); row/col offsets below are
    // compile-time immediates off the per-kd slice pointer.
    const u64* xb = xin + (size_t)n * IMG_F2
                  + ((ptrdiff_t)(h0 - 1) * W_DIM + (w0 - 1)) * C2 + lane;

    u64 acc[HS][WS];
    #pragma unroll
    for (int i = 0; i < HS; i++)
        #pragma unroll
        for (int j = 0; j < WS; j++)
            acc[i][j] = 0ull;

    #pragma unroll
    for (int kd = 0; kd < 3; kd++) {
        const int id = d + kd - 1;
        if (id < 0 || id >= D_DIM) continue;       // warp-uniform (d edges only)

        u64 wgt[3][3];
        #pragma unroll
        for (int kh = 0; kh < 3; kh++)
            #pragma unroll
            for (int kw = 0; kw < 3; kw++)
                wgt[kh][kw] = wb[((kd * 3 + kh) * 3 + kw) * C2];

        const u64* xs = xb + (size_t)id * SLICE_F2;

        #pragma unroll
        for (int r = 0; r < HS + 2; r++) {
            // row validity as a precomputed boolean: NO branch, NO comparison
            const bool hv = (r == 0) ? htop : (r == HS + 1) ? hbot : true;
            const u64* p = xs + r * ROW_F2;        // immediate-folded offsets

            u64 row[WS + 2];
            row[0] = (hv && lv) ? p[0] : 0ull;
            #pragma unroll
            for (int j = 1; j <= WS; j++)
                row[j] = hv ? p[j * C2] : 0ull;
            row[WS + 1] = (hv && rv) ? p[(WS + 1) * C2] : 0ull;

            #pragma unroll
            for (int oh = 0; oh < HS; oh++) {
                // input row ih = h0 + r - 1 feeds output oh with tap k = r - oh
                const int k = r - oh;
                if (k >= 0 && k < 3) {
                    #pragma unroll
                    for (int ow = 0; ow < WS; ow++)
                        #pragma unroll
                        for (int kw = 0; kw < 3; kw++)
                            fma2(acc[oh][ow], row[ow + kw], wgt[k][kw]);
                }
            }
        }
    }

    u64* o = out + (size_t)n * IMG_F2 + (size_t)d * SLICE_F2
           + ((size_t)h0 * W_DIM + w0) * C2 + lane;
    #pragma unroll
    for (int i = 0; i < HS; i++)
        #pragma unroll
        for (int j = 0; j < WS; j++)
            o[(i * W_DIM + j) * C2] = acc[i][j];
}

extern "C" void kernel_launch(void* const* d_in, const int* in_sizes, int n_in,
                              void* d_out, int out_size) {
    const u64* x = (const u64*)d_in[0];
    const u64* w = (const u64*)d_in[1];
    u64* o = (u64*)d_out;

    // total warps = N * D * HT2 * WSEG = 4*16*56*16 = 57344
    const int total_warps = N_DIM * D_DIM * HT2 * WSEG;
    dwconv3d_kernel<<<total_warps / WPB, TPB>>>(x, w, o);
}